// round 5
// baseline (speedup 1.0000x reference)
#include <cuda_runtime.h>
#include <cuda_bf16.h>
#include <cstdint>
#include <cstddef>

#define Dm 1024
#define FFNm 4096
#define SEGm 128
#define LLm 256
#define MMm 4
#define BBm 64
#define UUm 128
#define RRm 32
#define TTm 160
#define QQm 161
#define KKm 420
#define BD (BBm*Dm)
#define NEG_INF_F (-1e8f)
#define EPS_LN 1e-5f
#define S0_OFF 0u
#define S1_OFF 8388608u
#define S2_OFF 10485760u
#define S3_OFF 10551296u
#define S4_OFF 10813440u
#define S5_OFF 27590656u

typedef __nv_bfloat16 bf16;
typedef __nv_bfloat162 bf162;

__device__ float g_cat[165*BD];
__device__ float g_q[QQm*BD];
__device__ float g_k[KKm*BD];
__device__ float g_v[KKm*BD];
__device__ float g_scores[(size_t)1024*QQm*KKm];
__device__ float g_attn[QQm*BD];
__device__ float g_out[QQm*BD];
__device__ float g_res[TTm*BD];
__device__ float g_ff2[TTm*BD];
__device__ bf16 g_cat_h[165*BD], g_cat_l[165*BD];
__device__ bf16 g_ffin_h[TTm*BD], g_ffin_l[TTm*BD];
__device__ bf16 g_ffh_h[(size_t)TTm*BBm*FFNm], g_ffh_l[(size_t)TTm*BBm*FFNm];
__device__ bf16 g_attn_h[QQm*BD], g_attn_l[QQm*BD];
__device__ bf16 g_wq_h[Dm*Dm], g_wq_l[Dm*Dm];
__device__ bf16 g_wkv_h[2*Dm*Dm], g_wkv_l[2*Dm*Dm];
__device__ bf16 g_wo_h[Dm*Dm], g_wo_l[Dm*Dm];
__device__ bf16 g_w1_h[FFNm*Dm], g_w1_l[FFNm*Dm];
__device__ bf16 g_w2_h[Dm*FFNm], g_w2_l[Dm*FFNm];

__device__ __forceinline__ uint32_t smem_u32(const void* p){
    uint32_t a; asm("{ .reg .u64 t; cvta.to.shared.u64 t, %1; cvt.u32.u64 %0, t; }":"=r"(a):"l"(p)); return a;
}
__device__ __forceinline__ void cp16(uint32_t dst, const void* src){
    asm volatile("cp.async.cg.shared.global [%0], [%1], 16;"::"r"(dst),"l"(src));
}
__device__ __forceinline__ void ldsm4(uint32_t* r, uint32_t addr){
    asm volatile("ldmatrix.sync.aligned.m8n8.x4.shared.b16 {%0,%1,%2,%3}, [%4];"
        :"=r"(r[0]),"=r"(r[1]),"=r"(r[2]),"=r"(r[3]):"r"(addr));
}
__device__ __forceinline__ void mma16816(float* c, const uint32_t* a, uint32_t b0, uint32_t b1){
    asm volatile("mma.sync.aligned.m16n8k16.row.col.f32.bf16.bf16.f32 "
        "{%0,%1,%2,%3}, {%4,%5,%6,%7}, {%8,%9}, {%0,%1,%2,%3};"
        :"+f"(c[0]),"+f"(c[1]),"+f"(c[2]),"+f"(c[3])
        :"r"(a[0]),"r"(a[1]),"r"(a[2]),"r"(a[3]),"r"(b0),"r"(b1));
}

// ---- HMMA split-bf16 GEMM v2: fused 3-combo, 3-stage pipe, tile 128x128, BK=32 ----
// modes: 0 = fp32 C0 (+bias); 1 = split C1h/C1l (+bias, relu); 2 = KV (remap + mirror)
#define ROWB 80
#define TILEB 10240
#define STAGEB 40960
#define STG 3
#define GEMM_SMEM (STG*STAGEB)
__global__ void __launch_bounds__(256) gemm_mma(
    const bf16* __restrict__ Ah_, const bf16* __restrict__ Al_, int lda,
    const bf16* __restrict__ Bh_, const bf16* __restrict__ Bl_, int ldb,
    const float* __restrict__ bias, int M, int K, int mode,
    float* __restrict__ C0, bf16* __restrict__ C1h, bf16* __restrict__ C1l, int ldc,
    float* __restrict__ Ck, float* __restrict__ Cv,
    float* __restrict__ km, float* __restrict__ vm)
{
    extern __shared__ __align__(16) char smem[];
    const int tid=threadIdx.x, wid=tid>>5, lane=tid&31;
    const int m0=blockIdx.y*128, n0=blockIdx.x*128;
    const int m0w=(wid>>1)*32, n0w=(wid&1)*64;
    const uint32_t sb=smem_u32(smem);
    const int nIt=K>>5;

    float acc[2][8][4];
#pragma unroll
    for(int i=0;i<2;i++)
#pragma unroll
        for(int j=0;j<8;j++)
#pragma unroll
            for(int l=0;l<4;l++) acc[i][j][l]=0.f;

    const int lrow=tid>>1, le0=(tid&1)*16;   // element offset 0 or 16 within 32-wide chunk
    int gra = m0+lrow; if(gra>=M) gra=M-1;
    const int grb = n0+lrow;

    auto load_stage=[&](int it){
        int kk=it<<5;
        uint32_t st=sb+(it%STG)*STAGEB;
        uint32_t rb=st+(uint32_t)lrow*ROWB+le0*2;
        cp16(rb,          Ah_+(size_t)gra*lda+kk+le0);
        cp16(rb+16,       Ah_+(size_t)gra*lda+kk+le0+8);
        cp16(rb+TILEB,    Al_+(size_t)gra*lda+kk+le0);
        cp16(rb+TILEB+16, Al_+(size_t)gra*lda+kk+le0+8);
        cp16(rb+2*TILEB,    Bh_+(size_t)grb*ldb+kk+le0);
        cp16(rb+2*TILEB+16, Bh_+(size_t)grb*ldb+kk+le0+8);
        cp16(rb+3*TILEB,    Bl_+(size_t)grb*ldb+kk+le0);
        cp16(rb+3*TILEB+16, Bl_+(size_t)grb*ldb+kk+le0+8);
        asm volatile("cp.async.commit_group;":::"memory");
    };

    load_stage(0); load_stage(1);
    for(int it=0; it<nIt; ++it){
        asm volatile("cp.async.wait_group 1;":::"memory");
        __syncthreads();
        uint32_t st=sb+(it%STG)*STAGEB;
        uint32_t aoff=st+(uint32_t)(m0w+(lane&15))*ROWB+((lane>>4)<<4);
        uint32_t boff=st+2*TILEB+(uint32_t)(n0w+(lane&7)+((lane>>4)<<3))*ROWB+(((lane>>3)&1)<<4);
#pragma unroll
        for(int ks=0;ks<2;++ks){
            uint32_t ah[2][4], al[2][4], bh[4][4], bl[4][4];
            ldsm4(ah[0], aoff+ks*32);
            ldsm4(ah[1], aoff+16*ROWB+ks*32);
            ldsm4(al[0], aoff+TILEB+ks*32);
            ldsm4(al[1], aoff+TILEB+16*ROWB+ks*32);
#pragma unroll
            for(int np=0;np<4;++np){
                ldsm4(bh[np], boff+np*16*ROWB+ks*32);
                ldsm4(bl[np], boff+TILEB+np*16*ROWB+ks*32);
            }
#pragma unroll
            for(int mt=0;mt<2;++mt)
#pragma unroll
                for(int nt=0;nt<8;++nt){
                    int p=nt>>1,h=(nt&1)<<1;
                    mma16816(acc[mt][nt], ah[mt], bh[p][h], bh[p][h+1]);
                    mma16816(acc[mt][nt], ah[mt], bl[p][h], bl[p][h+1]);
                    mma16816(acc[mt][nt], al[mt], bh[p][h], bh[p][h+1]);
                }
        }
        __syncthreads();
        if(it+2<nIt) load_stage(it+2);
    }

    // epilogue
#pragma unroll
    for(int mt=0;mt<2;++mt){
        int rr=m0+m0w+mt*16+(lane>>2);
#pragma unroll
        for(int nt=0;nt<8;++nt){
            int c=n0+n0w+nt*8+((lane&3)<<1);
            float b0=bias?__ldg(bias+c):0.f, b1=bias?__ldg(bias+c+1):0.f;
#pragma unroll
            for(int hr=0;hr<2;++hr){
                int r=rr+hr*8;
                if(r>=M) continue;
                float v0=acc[mt][nt][hr*2]+b0, v1=acc[mt][nt][hr*2+1]+b1;
                if(mode==1){
                    v0=fmaxf(v0,0.f); v1=fmaxf(v1,0.f);
                    bf16 h0=__float2bfloat16(v0), h1=__float2bfloat16(v1);
                    bf16 l0=__float2bfloat16(v0-__bfloat162float(h0));
                    bf16 l1=__float2bfloat16(v1-__bfloat162float(h1));
                    *(uint32_t*)(C1h+(size_t)r*ldc+c)=(uint32_t)__bfloat16_as_ushort(h0)|((uint32_t)__bfloat16_as_ushort(h1)<<16);
                    *(uint32_t*)(C1l+(size_t)r*ldc+c)=(uint32_t)__bfloat16_as_ushort(l0)|((uint32_t)__bfloat16_as_ushort(l1)<<16);
                } else if(mode==0){
                    *(float2*)(C0+(size_t)r*ldc+c)=make_float2(v0,v1);
                } else {
                    int rk=r+(r>=2304?16384:0);
                    float2 val=make_float2(v0,v1);
                    if(c<1024){
                        *(float2*)(Ck+(size_t)rk*1024+c)=val;
                        if(r>=2304) *(float2*)(km+(size_t)(rk-18688)*1024+c)=val;
                    } else {
                        *(float2*)(Cv+(size_t)rk*1024+(c-1024))=val;
                        if(r>=2304) *(float2*)(vm+(size_t)(rk-18688)*1024+(c-1024))=val;
                    }
                }
            }
        }
    }
}

// ---- fp32 -> (hi,lo) bf16 split ----
__device__ __forceinline__ void split4(float4 v, bf162* hp, bf162* lp, size_t i2){
    bf16 h0=__float2bfloat16(v.x), h1=__float2bfloat16(v.y);
    bf16 h2=__float2bfloat16(v.z), h3=__float2bfloat16(v.w);
    hp[i2]=__halves2bfloat162(h0,h1); hp[i2+1]=__halves2bfloat162(h2,h3);
    lp[i2]=__halves2bfloat162(__float2bfloat16(v.x-__bfloat162float(h0)),__float2bfloat16(v.y-__bfloat162float(h1)));
    lp[i2+1]=__halves2bfloat162(__float2bfloat16(v.z-__bfloat162float(h2)),__float2bfloat16(v.w-__bfloat162float(h3)));
}
__global__ void k_split(const float* __restrict__ s, bf16* __restrict__ h, bf16* __restrict__ l){
    size_t i=(size_t)blockIdx.x*blockDim.x+threadIdx.x;
    split4(((const float4*)s)[i], (bf162*)h, (bf162*)l, 2*i);
}

__device__ __forceinline__ float bsum(float v, float* sh){
    int lane=threadIdx.x&31, w=threadIdx.x>>5;
#pragma unroll
    for(int o=16;o;o>>=1) v+=__shfl_xor_sync(0xffffffffu,v,o);
    if(lane==0) sh[w]=v;
    __syncthreads();
    if(w==0){ float r=(lane<8)?sh[lane]:0.f;
#pragma unroll
        for(int o=4;o;o>>=1) r+=__shfl_xor_sync(0xffffffffu,r,o);
        if(lane==0) sh[0]=r; }
    __syncthreads(); float o=sh[0]; __syncthreads(); return o;
}
__device__ __forceinline__ float4 ln_core(float4 x, const float* gw, const float* bw, int tid, float* sh){
    float mu=bsum(x.x+x.y+x.z+x.w,sh)*(1.f/Dm);
    float d0=x.x-mu,d1=x.y-mu,d2=x.z-mu,d3=x.w-mu;
    float var=bsum(d0*d0+d1*d1+d2*d2+d3*d3,sh)*(1.f/Dm);
    float inv=rsqrtf(var+EPS_LN);
    float4 g4=((const float4*)gw)[tid], b4=((const float4*)bw)[tid];
    return make_float4(d0*inv*g4.x+b4.x, d1*inv*g4.y+b4.y, d2*inv*g4.z+b4.z, d3*inv*g4.w+b4.w);
}
__global__ void __launch_bounds__(256) k_ln_in(const float* __restrict__ rc, const float* __restrict__ utt,
                                               const float* __restrict__ gw, const float* __restrict__ bw){
    __shared__ float sh[8];
    int row=blockIdx.x, tid=threadIdx.x;
    const float* src=(row<RRm*BBm)?rc+(size_t)row*Dm:utt+(size_t)(row-RRm*BBm)*Dm;
    float4 o=ln_core(((const float4*)src)[tid],gw,bw,tid,sh);
    size_t base=(size_t)(4*BBm+row)*Dm;
    ((float4*)(g_cat+base))[tid]=o;
    split4(o,(bf162*)(g_cat_h+base),(bf162*)(g_cat_l+base),2*(size_t)tid);
}
__global__ void __launch_bounds__(256) k_ln_ff(const float* __restrict__ gw, const float* __restrict__ bw){
    __shared__ float sh[8];
    int row=blockIdx.x, tid=threadIdx.x;
    size_t base=(size_t)row*Dm;
    float4 o=ln_core(((const float4*)(g_res+base))[tid],gw,bw,tid,sh);
    split4(o,(bf162*)(g_ffin_h+base),(bf162*)(g_ffin_l+base),2*(size_t)tid);
}
__global__ void __launch_bounds__(256) k_ln_final(const float* __restrict__ gw, const float* __restrict__ bw,
                                                  float* __restrict__ dout){
    __shared__ float sh[8];
    int row=blockIdx.x, tid=threadIdx.x;
    float4 a=((const float4*)(g_res+(size_t)row*Dm))[tid];
    float4 f=((const float4*)(g_ff2+(size_t)row*Dm))[tid];
    float4 o=ln_core(make_float4(a.x+f.x,a.y+f.y,a.z+f.z,a.w+f.w),gw,bw,tid,sh);
    float* dst=(row<RRm*BBm)?dout+S1_OFF+(size_t)row*Dm:dout+S0_OFF+(size_t)(row-RRm*BBm)*Dm;
    ((float4*)dst)[tid]=o;
}
__global__ void k_summary(){
    int e=blockIdx.x*blockDim.x+threadIdx.x;
    float s=0.f;
#pragma unroll 8
    for(int t=0;t<UUm;t++) s+=g_cat[(size_t)(36+t)*BD+e];
    float v=s*(1.f/SEGm);
    size_t o=(size_t)164*BD+e;
    bf16 h=__float2bfloat16(v);
    g_cat_h[o]=h; g_cat_l[o]=__float2bfloat16(v-__bfloat162float(h));
}

// ---- SIMT NT gemm (scores) ----
__global__ void __launch_bounds__(256) gemm_nt(
    const float* __restrict__ A, int lda, long sAz,
    const float* __restrict__ W, int ldw, long sWz,
    float* __restrict__ C, int ldc, long sCz, int M, int N, int K, float alpha)
{
    __shared__ float As[16][132];
    __shared__ float Ws[16][68];
    A+=(long)blockIdx.z*sAz; W+=(long)blockIdx.z*sWz; C+=(long)blockIdx.z*sCz;
    const int bm0=blockIdx.y*128, bn0=blockIdx.x*64;
    const int tid=threadIdx.x, tx=tid&15, ty=tid>>4;
    const int ar=tid>>1, ak=(tid&1)*8, wr=tid>>2, wk=(tid&3)*4;
    const bool av=(bm0+ar)<M, wv=(bn0+wr)<N;
    const float* Ap=A+(size_t)(bm0+ar)*lda+ak;
    const float* Wp=W+(size_t)(bn0+wr)*ldw+wk;
    float acc[8][4];
#pragma unroll
    for(int i=0;i<8;i++)
#pragma unroll
        for(int j=0;j<4;j++) acc[i][j]=0.f;
    for(int k0=0;k0<K;k0+=16){
        float4 a0=make_float4(0,0,0,0),a1=a0,w0=a0;
        if(av){a0=*(const float4*)(Ap+k0); a1=*(const float4*)(Ap+k0+4);}
        if(wv) w0=*(const float4*)(Wp+k0);
        As[ak+0][ar]=a0.x;As[ak+1][ar]=a0.y;As[ak+2][ar]=a0.z;As[ak+3][ar]=a0.w;
        As[ak+4][ar]=a1.x;As[ak+5][ar]=a1.y;As[ak+6][ar]=a1.z;As[ak+7][ar]=a1.w;
        Ws[wk+0][wr]=w0.x;Ws[wk+1][wr]=w0.y;Ws[wk+2][wr]=w0.z;Ws[wk+3][wr]=w0.w;
        __syncthreads();
#pragma unroll
        for(int kk=0;kk<16;kk++){
            float4 f0=*(const float4*)&As[kk][ty*8], f1=*(const float4*)&As[kk][ty*8+4];
            float4 bf=*(const float4*)&Ws[kk][tx*4];
            float avv[8]={f0.x,f0.y,f0.z,f0.w,f1.x,f1.y,f1.z,f1.w};
            float bv[4]={bf.x,bf.y,bf.z,bf.w};
#pragma unroll
            for(int i=0;i<8;i++)
#pragma unroll
                for(int j=0;j<4;j++) acc[i][j]+=avv[i]*bv[j];
        }
        __syncthreads();
    }
#pragma unroll
    for(int i=0;i<8;i++){
        int r=bm0+ty*8+i; if(r>=M) continue;
#pragma unroll
        for(int j=0;j<4;j++){
            int c=bn0+tx*4+j; if(c>=N) continue;
            C[(size_t)r*ldc+c]=acc[i][j]*alpha;
        }
    }
}
// ---- SIMT NN gemm (P@V) ----
__global__ void __launch_bounds__(256) gemm_nn(
    const float* __restrict__ A, int lda, long sAz,
    const float* __restrict__ Bm, int ldb, long sBz,
    float* __restrict__ C, int ldc, long sCz, int M, int N, int K)
{
    __shared__ float As[16][132];
    __shared__ float Bs[16][68];
    A+=(long)blockIdx.z*sAz; Bm+=(long)blockIdx.z*sBz; C+=(long)blockIdx.z*sCz;
    const int bm0=blockIdx.y*128, bn0=blockIdx.x*64;
    const int tid=threadIdx.x, tx=tid&15, ty=tid>>4;
    const int ar=tid>>1, ak=(tid&1)*8, br=tid>>4, bc=(tid&15)*4;
    const bool av=(bm0+ar)<M, bnv=(bn0+bc)<N;
    const float* Ap=A+(size_t)(bm0+ar)*lda+ak;
    float acc[8][4];
#pragma unroll
    for(int i=0;i<8;i++)
#pragma unroll
        for(int j=0;j<4;j++) acc[i][j]=0.f;
    for(int k0=0;k0<K;k0+=16){
        float4 a0=make_float4(0,0,0,0),a1=a0,b0=a0;
        if(av){ if(k0+ak<K) a0=*(const float4*)(Ap+k0); if(k0+ak+4<K) a1=*(const float4*)(Ap+k0+4); }
        if((k0+br)<K && bnv) b0=*(const float4*)(Bm+(size_t)(k0+br)*ldb+bn0+bc);
        As[ak+0][ar]=a0.x;As[ak+1][ar]=a0.y;As[ak+2][ar]=a0.z;As[ak+3][ar]=a0.w;
        As[ak+4][ar]=a1.x;As[ak+5][ar]=a1.y;As[ak+6][ar]=a1.z;As[ak+7][ar]=a1.w;
        Bs[br][bc+0]=b0.x;Bs[br][bc+1]=b0.y;Bs[br][bc+2]=b0.z;Bs[br][bc+3]=b0.w;
        __syncthreads();
#pragma unroll
        for(int kk=0;kk<16;kk++){
            float4 f0=*(const float4*)&As[kk][ty*8], f1=*(const float4*)&As[kk][ty*8+4];
            float4 bf=*(const float4*)&Bs[kk][tx*4];
            float avv[8]={f0.x,f0.y,f0.z,f0.w,f1.x,f1.y,f1.z,f1.w};
            float bv[4]={bf.x,bf.y,bf.z,bf.w};
#pragma unroll
            for(int i=0;i<8;i++)
#pragma unroll
                for(int j=0;j<4;j++) acc[i][j]+=avv[i]*bv[j];
        }
        __syncthreads();
    }
#pragma unroll
    for(int i=0;i<8;i++){
        int r=bm0+ty*8+i; if(r>=M) continue;
#pragma unroll
        for(int j=0;j<4;j++){
            int c=bn0+tx*4+j; if(c>=N) continue;
            C[(size_t)r*ldc+c]=acc[i][j];
        }
    }
}

__global__ void __launch_bounds__(128) k_softmax(const int* __restrict__ past_len){
    __shared__ float sred[4];
    int idx=blockIdx.x, q=idx%QQm, bh=idx/QQm;
    float* row=g_scores+(size_t)bh*(QQm*KKm)+(size_t)q*KKm;
    int pl=past_len[0], m_kv=min(LLm,pl), m_m=min(MMm,pl/SEGm);
    int tid=threadIdx.x, lane=tid&31, w=tid>>5;
    float v[4], mx=-3.4e38f;
#pragma unroll
    for(int j=0;j<4;j++){
        int c=tid+128*j; float val=-3.4e38f;
        if(c<KKm){
            bool msk=(c<MMm-m_m)||(c>=MMm+RRm && c<MMm+RRm+(LLm-m_kv))||(q==QQm-1 && c<MMm);
            val=msk?NEG_INF_F:row[c];
        }
        v[j]=val; mx=fmaxf(mx,val);
    }
#pragma unroll
    for(int o=16;o;o>>=1) mx=fmaxf(mx,__shfl_xor_sync(0xffffffffu,mx,o));
    if(lane==0) sred[w]=mx;
    __syncthreads();
    mx=fmaxf(fmaxf(sred[0],sred[1]),fmaxf(sred[2],sred[3]));
    __syncthreads();
    float s=0.f;
#pragma unroll
    for(int j=0;j<4;j++){ int c=tid+128*j; if(c<KKm){ v[j]=expf(v[j]-mx); s+=v[j]; } }
#pragma unroll
    for(int o=16;o;o>>=1) s+=__shfl_xor_sync(0xffffffffu,s,o);
    if(lane==0) sred[w]=s;
    __syncthreads();
    s=sred[0]+sred[1]+sred[2]+sred[3];
    float r=1.f/s;
#pragma unroll
    for(int j=0;j<4;j++){ int c=tid+128*j; if(c<KKm) row[c]=v[j]*r; }
}

__global__ void k_resadd(const float* __restrict__ rc, const float* __restrict__ utt){
    size_t i=(size_t)blockIdx.x*blockDim.x+threadIdx.x;
    float4 o=((const float4*)g_out)[i];
    size_t rc4=(size_t)RRm*BD/4;
    float4 s=(i<rc4)?((const float4*)rc)[i]:((const float4*)utt)[i-rc4];
    ((float4*)g_res)[i]=make_float4(o.x+s.x,o.y+s.y,o.z+s.z,o.w+s.w);
}
__global__ void k_clip(float* __restrict__ dout){
    size_t i=(size_t)blockIdx.x*blockDim.x+threadIdx.x;
    float4 v=((const float4*)(g_out+(size_t)TTm*BD))[i];
    v.x=fminf(fmaxf(v.x,-10.f),10.f); v.y=fminf(fmaxf(v.y,-10.f),10.f);
    v.z=fminf(fmaxf(v.z,-10.f),10.f); v.w=fminf(fmaxf(v.w,-10.f),10.f);
    ((float4*)(dout+S2_OFF))[i]=v;
}

extern "C" void kernel_launch(void* const* d_in, const int* in_sizes, int n_in,
                              void* d_out_v, int out_size) {
    const float* utterance=(const float*)d_in[0];
    const float* right_ctx=(const float*)d_in[1];
    const float* mems_in=(const float*)d_in[2];
    const float* state_mems=(const float*)d_in[3];
    const float* lc_key=(const float*)d_in[4];
    const float* lc_val=(const float*)d_in[5];
    const float* b_kv=(const float*)d_in[7];
    const float* W_kv=(const float*)d_in[6];
    const float* W_q=(const float*)d_in[8];
    const float* b_q=(const float*)d_in[9];
    const float* W_out=(const float*)d_in[10];
    const float* b_out=(const float*)d_in[11];
    const float* ln_in_g=(const float*)d_in[12];
    const float* ln_in_b=(const float*)d_in[13];
    const float* ln_ff_g=(const float*)d_in[14];
    const float* ln_ff_b=(const float*)d_in[15];
    const float* W_ff1=(const float*)d_in[16];
    const float* b_ff1=(const float*)d_in[17];
    const float* W_ff2=(const float*)d_in[18];
    const float* b_ff2=(const float*)d_in[19];
    const float* ln_out_g=(const float*)d_in[20];
    const float* ln_out_b=(const float*)d_in[21];
    const int* past_len=(const int*)d_in[22];
    float* dout=(float*)d_out_v;

    float *q,*k,*v,*scores,*attn,*outb,*ff2b;
    bf16 *cath,*catl,*ffinh,*ffinl,*ffhh,*ffhl,*attnh,*attnl;
    bf16 *wqh,*wql,*wkvh,*wkvl,*woh,*wol,*w1h,*w1l,*w2h,*w2l;
    cudaGetSymbolAddress((void**)&q,g_q); cudaGetSymbolAddress((void**)&k,g_k);
    cudaGetSymbolAddress((void**)&v,g_v); cudaGetSymbolAddress((void**)&scores,g_scores);
    cudaGetSymbolAddress((void**)&attn,g_attn); cudaGetSymbolAddress((void**)&outb,g_out);
    cudaGetSymbolAddress((void**)&ff2b,g_ff2);
    cudaGetSymbolAddress((void**)&cath,g_cat_h); cudaGetSymbolAddress((void**)&catl,g_cat_l);
    cudaGetSymbolAddress((void**)&ffinh,g_ffin_h); cudaGetSymbolAddress((void**)&ffinl,g_ffin_l);
    cudaGetSymbolAddress((void**)&ffhh,g_ffh_h); cudaGetSymbolAddress((void**)&ffhl,g_ffh_l);
    cudaGetSymbolAddress((void**)&attnh,g_attn_h); cudaGetSymbolAddress((void**)&attnl,g_attn_l);
    cudaGetSymbolAddress((void**)&wqh,g_wq_h); cudaGetSymbolAddress((void**)&wql,g_wq_l);
    cudaGetSymbolAddress((void**)&wkvh,g_wkv_h); cudaGetSymbolAddress((void**)&wkvl,g_wkv_l);
    cudaGetSymbolAddress((void**)&woh,g_wo_h); cudaGetSymbolAddress((void**)&wol,g_wo_l);
    cudaGetSymbolAddress((void**)&w1h,g_w1_h); cudaGetSymbolAddress((void**)&w1l,g_w1_l);
    cudaGetSymbolAddress((void**)&w2h,g_w2_h); cudaGetSymbolAddress((void**)&w2l,g_w2_l);

    cudaFuncSetAttribute(gemm_mma, cudaFuncAttributeMaxDynamicSharedMemorySize, GEMM_SMEM);

    // splits
    k_split<<<(4*BD/4)/256,256>>>(state_mems, cath, catl);
    k_split<<<(Dm*Dm/4)/256,256>>>(W_q, wqh, wql);
    k_split<<<(2*Dm*Dm/4)/256,256>>>(W_kv, wkvh, wkvl);
    k_split<<<(Dm*Dm/4)/256,256>>>(W_out, woh, wol);
    k_split<<<((size_t)FFNm*Dm/4)/256,256>>>(W_ff1, w1h, w1l);
    k_split<<<((size_t)FFNm*Dm/4)/256,256>>>(W_ff2, w2h, w2l);
    // LN + summary
    k_ln_in<<<TTm*BBm,256>>>(right_ctx, utterance, ln_in_g, ln_in_b);
    k_summary<<<BD/256,256>>>();
    // Q projection (mode 0)
    gemm_mma<<<dim3(8,81),256,GEMM_SMEM>>>(cath+(size_t)4*BD, catl+(size_t)4*BD, Dm, wqh, wql, Dm,
        b_q, QQm*BBm, Dm, 0, q, nullptr, nullptr, Dm, nullptr, nullptr, nullptr, nullptr);
    // merged KV projection (mode 2, with mirror into dout)
    gemm_mma<<<dim3(16,82),256,GEMM_SMEM>>>(cath, catl, Dm, wkvh, wkvl, Dm,
        b_kv, 164*BBm, Dm, 2, nullptr, nullptr, nullptr, 0,
        k, v, dout+S4_OFF+(size_t)128*BD, dout+S5_OFF+(size_t)128*BD);
    cudaMemcpyAsync(k+(size_t)36*BD, lc_key, (size_t)LLm*BD*sizeof(float), cudaMemcpyDeviceToDevice, 0);
    cudaMemcpyAsync(v+(size_t)36*BD, lc_val, (size_t)LLm*BD*sizeof(float), cudaMemcpyDeviceToDevice, 0);
    // attention (SIMT fp32)
    gemm_nt<<<dim3(7,2,1024),256>>>(q, BD, 64, k, BD, 64, scores, KKm, (long)QQm*KKm, QQm, KKm, 64, 0.125f);
    k_softmax<<<1024*QQm,128>>>(past_len);
    gemm_nn<<<dim3(1,2,1024),256>>>(scores, KKm, (long)QQm*KKm, v, BD, 64, attn, BD, 64, QQm, 64, KKm);
    // out proj
    k_split<<<((size_t)QQm*BD/4)/256,256>>>(attn, attnh, attnl);
    gemm_mma<<<dim3(8,81),256,GEMM_SMEM>>>(attnh, attnl, Dm, woh, wol, Dm,
        b_out, QQm*BBm, Dm, 0, outb, nullptr, nullptr, Dm, nullptr, nullptr, nullptr, nullptr);
    k_resadd<<<(TTm*BD/4)/256,256>>>(right_ctx, utterance);
    k_clip<<<(BD/4)/256,256>>>(dout);
    // FFN
    k_ln_ff<<<TTm*BBm,256>>>(ln_ff_g, ln_ff_b);
    gemm_mma<<<dim3(32,80),256,GEMM_SMEM>>>(ffinh, ffinl, Dm, w1h, w1l, Dm,
        b_ff1, TTm*BBm, Dm, 1, nullptr, ffhh, ffhl, FFNm, nullptr, nullptr, nullptr, nullptr);
    gemm_mma<<<dim3(8,80),256,GEMM_SMEM>>>(ffhh, ffhl, FFNm, w2h, w2l, FFNm,
        b_ff2, TTm*BBm, FFNm, 0, ff2b, nullptr, nullptr, Dm, nullptr, nullptr, nullptr, nullptr);
    k_ln_final<<<TTm*BBm,256>>>(ln_out_g, ln_out_b, dout);
    // state-carry (lc halves; new rows mirrored by KV gemm epilogue)
    cudaMemcpyAsync(dout+S3_OFF, state_mems+BD, (size_t)3*BD*sizeof(float), cudaMemcpyDeviceToDevice, 0);
    cudaMemcpyAsync(dout+S3_OFF+(size_t)3*BD, mems_in, (size_t)BD*sizeof(float), cudaMemcpyDeviceToDevice, 0);
    cudaMemcpyAsync(dout+S4_OFF, lc_key+(size_t)128*BD, (size_t)128*BD*sizeof(float), cudaMemcpyDeviceToDevice, 0);
    cudaMemcpyAsync(dout+S5_OFF, lc_val+(size_t)128*BD, (size_t)128*BD*sizeof(float), cudaMemcpyDeviceToDevice, 0);
}

// round 6
// speedup vs baseline: 1.1306x; 1.1306x over previous
#include <cuda_runtime.h>
#include <cuda_bf16.h>
#include <cstdint>
#include <cstddef>

#define Dm 1024
#define FFNm 4096
#define SEGm 128
#define LLm 256
#define MMm 4
#define BBm 64
#define UUm 128
#define RRm 32
#define TTm 160
#define QQm 161
#define KKm 420
#define BD (BBm*Dm)
#define NEG_INF_F (-1e8f)
#define EPS_LN 1e-5f
#define S0_OFF 0u
#define S1_OFF 8388608u
#define S2_OFF 10485760u
#define S3_OFF 10551296u
#define S4_OFF 10813440u
#define S5_OFF 27590656u

typedef __nv_bfloat16 bf16;
typedef __nv_bfloat162 bf162;

__device__ float g_cat[165*BD];
__device__ float g_q[QQm*BD];
__device__ float g_k[KKm*BD];
__device__ float g_v[KKm*BD];
__device__ float g_scores[(size_t)1024*QQm*KKm];
__device__ float g_attn[QQm*BD];
__device__ float g_res[TTm*BD];
__device__ float g_ff2[TTm*BD];
__device__ bf16 g_cat_h[165*BD], g_cat_l[165*BD];
__device__ bf16 g_ffin_h[TTm*BD], g_ffin_l[TTm*BD];
__device__ bf16 g_ffh_h[(size_t)TTm*BBm*FFNm], g_ffh_l[(size_t)TTm*BBm*FFNm];
__device__ bf16 g_attn_h[QQm*BD], g_attn_l[QQm*BD];
__device__ bf16 g_wq_h[Dm*Dm], g_wq_l[Dm*Dm];
__device__ bf16 g_wkv_h[2*Dm*Dm], g_wkv_l[2*Dm*Dm];
__device__ bf16 g_wo_h[Dm*Dm], g_wo_l[Dm*Dm];
__device__ bf16 g_w1_h[FFNm*Dm], g_w1_l[FFNm*Dm];
__device__ bf16 g_w2_h[Dm*FFNm], g_w2_l[Dm*FFNm];

__device__ __forceinline__ uint32_t smem_u32(const void* p){
    uint32_t a; asm("{ .reg .u64 t; cvta.to.shared.u64 t, %1; cvt.u32.u64 %0, t; }":"=r"(a):"l"(p)); return a;
}
__device__ __forceinline__ void cp16(uint32_t dst, const void* src){
    asm volatile("cp.async.cg.shared.global [%0], [%1], 16;"::"r"(dst),"l"(src));
}
__device__ __forceinline__ void ldsm4(uint32_t* r, uint32_t addr){
    asm volatile("ldmatrix.sync.aligned.m8n8.x4.shared.b16 {%0,%1,%2,%3}, [%4];"
        :"=r"(r[0]),"=r"(r[1]),"=r"(r[2]),"=r"(r[3]):"r"(addr));
}
__device__ __forceinline__ void mma16816(float* c, const uint32_t* a, uint32_t b0, uint32_t b1){
    asm volatile("mma.sync.aligned.m16n8k16.row.col.f32.bf16.bf16.f32 "
        "{%0,%1,%2,%3}, {%4,%5,%6,%7}, {%8,%9}, {%0,%1,%2,%3};"
        :"+f"(c[0]),"+f"(c[1]),"+f"(c[2]),"+f"(c[3])
        :"r"(a[0]),"r"(a[1]),"r"(a[2]),"r"(a[3]),"r"(b0),"r"(b1));
}

// ---- HMMA split-bf16 GEMM v3: fused 3-combo, 2-stage, 2 CTA/SM, tile 128x128, BK=32 ----
// mode 0: fp32 C0 (+bias) | 1: split C1h/l (+bias,relu) | 2: KV remap+mirror | 3: Wout residual+clip
#define ROWB 80
#define TILEB 10240
#define STAGEB 40960
#define GEMM_SMEM (2*STAGEB)
__global__ void __launch_bounds__(256,2) gemm_mma(
    const bf16* __restrict__ Ah_, const bf16* __restrict__ Al_, int lda,
    const bf16* __restrict__ Bh_, const bf16* __restrict__ Bl_, int ldb,
    const float* __restrict__ bias, int M, int K, int mode,
    float* __restrict__ C0, bf16* __restrict__ C1h, bf16* __restrict__ C1l, int ldc,
    float* __restrict__ Ck, float* __restrict__ Cv,
    float* __restrict__ km, float* __restrict__ vm)
{
    extern __shared__ __align__(16) char smem[];
    const int tid=threadIdx.x, wid=tid>>5, lane=tid&31;
    const int m0=blockIdx.y*128, n0=blockIdx.x*128;
    const int m0w=(wid>>1)*32, n0w=(wid&1)*64;
    const uint32_t sb=smem_u32(smem);
    const int nIt=K>>5;

    float acc[2][8][4];
#pragma unroll
    for(int i=0;i<2;i++)
#pragma unroll
        for(int j=0;j<8;j++)
#pragma unroll
            for(int l=0;l<4;l++) acc[i][j][l]=0.f;

    const int lrow=tid>>1, le0=(tid&1)*16;
    int gra=m0+lrow; if(gra>=M) gra=M-1;
    const int grb=n0+lrow;

    auto load_stage=[&](int it){
        int kk=it<<5;
        uint32_t st=sb+(it&1)*STAGEB;
        uint32_t rb=st+(uint32_t)lrow*ROWB+le0*2;
        cp16(rb,          Ah_+(size_t)gra*lda+kk+le0);
        cp16(rb+16,       Ah_+(size_t)gra*lda+kk+le0+8);
        cp16(rb+TILEB,    Al_+(size_t)gra*lda+kk+le0);
        cp16(rb+TILEB+16, Al_+(size_t)gra*lda+kk+le0+8);
        cp16(rb+2*TILEB,    Bh_+(size_t)grb*ldb+kk+le0);
        cp16(rb+2*TILEB+16, Bh_+(size_t)grb*ldb+kk+le0+8);
        cp16(rb+3*TILEB,    Bl_+(size_t)grb*ldb+kk+le0);
        cp16(rb+3*TILEB+16, Bl_+(size_t)grb*ldb+kk+le0+8);
        asm volatile("cp.async.commit_group;":::"memory");
    };

    load_stage(0); load_stage(1);
    for(int it=0; it<nIt; ++it){
        asm volatile("cp.async.wait_group 1;":::"memory");
        __syncthreads();
        uint32_t st=sb+(it&1)*STAGEB;
        uint32_t aoff=st+(uint32_t)(m0w+(lane&15))*ROWB+((lane>>4)<<4);
        uint32_t boff=st+2*TILEB+(uint32_t)(n0w+(lane&7)+((lane>>4)<<3))*ROWB+(((lane>>3)&1)<<4);
#pragma unroll
        for(int ks=0;ks<2;++ks){
            uint32_t af[4][4], bb[4][4];
            ldsm4(af[0], aoff+ks*32);
            ldsm4(af[1], aoff+16*ROWB+ks*32);
            ldsm4(af[2], aoff+TILEB+ks*32);
            ldsm4(af[3], aoff+TILEB+16*ROWB+ks*32);
#pragma unroll
            for(int np=0;np<4;++np) ldsm4(bb[np], boff+np*16*ROWB+ks*32);
#pragma unroll
            for(int mt=0;mt<2;++mt)
#pragma unroll
                for(int nt=0;nt<8;++nt){
                    int p=nt>>1,h=(nt&1)<<1;
                    mma16816(acc[mt][nt], af[mt],   bb[p][h], bb[p][h+1]);
                    mma16816(acc[mt][nt], af[2+mt], bb[p][h], bb[p][h+1]);
                }
#pragma unroll
            for(int np=0;np<4;++np) ldsm4(bb[np], boff+TILEB+np*16*ROWB+ks*32);
#pragma unroll
            for(int mt=0;mt<2;++mt)
#pragma unroll
                for(int nt=0;nt<8;++nt){
                    int p=nt>>1,h=(nt&1)<<1;
                    mma16816(acc[mt][nt], af[mt], bb[p][h], bb[p][h+1]);
                }
        }
        __syncthreads();
        if(it+2<nIt) load_stage(it+2);
    }

#pragma unroll
    for(int mt=0;mt<2;++mt){
        int rr=m0+m0w+mt*16+(lane>>2);
#pragma unroll
        for(int nt=0;nt<8;++nt){
            int c=n0+n0w+nt*8+((lane&3)<<1);
            float b0=bias?__ldg(bias+c):0.f, b1=bias?__ldg(bias+c+1):0.f;
#pragma unroll
            for(int hr=0;hr<2;++hr){
                int r=rr+hr*8;
                if(r>=M) continue;
                float v0=acc[mt][nt][hr*2]+b0, v1=acc[mt][nt][hr*2+1]+b1;
                if(mode==0){
                    *(float2*)(C0+(size_t)r*ldc+c)=make_float2(v0,v1);
                } else if(mode==1){
                    v0=fmaxf(v0,0.f); v1=fmaxf(v1,0.f);
                    bf16 h0=__float2bfloat16(v0), h1=__float2bfloat16(v1);
                    bf16 l0=__float2bfloat16(v0-__bfloat162float(h0));
                    bf16 l1=__float2bfloat16(v1-__bfloat162float(h1));
                    *(uint32_t*)(C1h+(size_t)r*ldc+c)=(uint32_t)__bfloat16_as_ushort(h0)|((uint32_t)__bfloat16_as_ushort(h1)<<16);
                    *(uint32_t*)(C1l+(size_t)r*ldc+c)=(uint32_t)__bfloat16_as_ushort(l0)|((uint32_t)__bfloat16_as_ushort(l1)<<16);
                } else if(mode==2){
                    int rk=r+(r>=2304?16384:0);
                    float2 val=make_float2(v0,v1);
                    if(c<1024){
                        *(float2*)(Ck+(size_t)rk*1024+c)=val;
                        if(r>=2304) *(float2*)(km+(size_t)(rk-18688)*1024+c)=val;
                    } else {
                        *(float2*)(Cv+(size_t)rk*1024+(c-1024))=val;
                        if(r>=2304) *(float2*)(vm+(size_t)(rk-18688)*1024+(c-1024))=val;
                    }
                } else {
                    if(r<10240){
                        const float* resid=(r<2048)?Ck+(size_t)r*1024+c:Cv+(size_t)(r-2048)*1024+c;
                        float2 rv=*(const float2*)resid;
                        *(float2*)(C0+(size_t)r*1024+c)=make_float2(v0+rv.x,v1+rv.y);
                    } else {
                        v0=fminf(fmaxf(v0,-10.f),10.f); v1=fminf(fmaxf(v1,-10.f),10.f);
                        *(float2*)(km+(size_t)(r-10240)*1024+c)=make_float2(v0,v1);
                    }
                }
            }
        }
    }
}

// ---- fp32 -> (hi,lo) bf16 split ----
__device__ __forceinline__ void split4(float4 v, bf162* hp, bf162* lp, size_t i2){
    bf16 h0=__float2bfloat16(v.x), h1=__float2bfloat16(v.y);
    bf16 h2=__float2bfloat16(v.z), h3=__float2bfloat16(v.w);
    hp[i2]=__halves2bfloat162(h0,h1); hp[i2+1]=__halves2bfloat162(h2,h3);
    lp[i2]=__halves2bfloat162(__float2bfloat16(v.x-__bfloat162float(h0)),__float2bfloat16(v.y-__bfloat162float(h1)));
    lp[i2+1]=__halves2bfloat162(__float2bfloat16(v.z-__bfloat162float(h2)),__float2bfloat16(v.w-__bfloat162float(h3)));
}
__global__ void k_split(const float* __restrict__ s, bf16* __restrict__ h, bf16* __restrict__ l){
    size_t i=(size_t)blockIdx.x*blockDim.x+threadIdx.x;
    split4(((const float4*)s)[i], (bf162*)h, (bf162*)l, 2*i);
}

__device__ __forceinline__ float bsum(float v, float* sh){
    int lane=threadIdx.x&31, w=threadIdx.x>>5;
#pragma unroll
    for(int o=16;o;o>>=1) v+=__shfl_xor_sync(0xffffffffu,v,o);
    if(lane==0) sh[w]=v;
    __syncthreads();
    if(w==0){ float r=(lane<8)?sh[lane]:0.f;
#pragma unroll
        for(int o=4;o;o>>=1) r+=__shfl_xor_sync(0xffffffffu,r,o);
        if(lane==0) sh[0]=r; }
    __syncthreads(); float o=sh[0]; __syncthreads(); return o;
}
__device__ __forceinline__ float4 ln_core(float4 x, const float* gw, const float* bw, int tid, float* sh){
    float mu=bsum(x.x+x.y+x.z+x.w,sh)*(1.f/Dm);
    float d0=x.x-mu,d1=x.y-mu,d2=x.z-mu,d3=x.w-mu;
    float var=bsum(d0*d0+d1*d1+d2*d2+d3*d3,sh)*(1.f/Dm);
    float inv=rsqrtf(var+EPS_LN);
    float4 g4=((const float4*)gw)[tid], b4=((const float4*)bw)[tid];
    return make_float4(d0*inv*g4.x+b4.x, d1*inv*g4.y+b4.y, d2*inv*g4.z+b4.z, d3*inv*g4.w+b4.w);
}
__global__ void __launch_bounds__(256) k_ln_in(const float* __restrict__ rc, const float* __restrict__ utt,
                                               const float* __restrict__ gw, const float* __restrict__ bw){
    __shared__ float sh[8];
    int row=blockIdx.x, tid=threadIdx.x;
    const float* src=(row<RRm*BBm)?rc+(size_t)row*Dm:utt+(size_t)(row-RRm*BBm)*Dm;
    float4 o=ln_core(((const float4*)src)[tid],gw,bw,tid,sh);
    size_t base=(size_t)(4*BBm+row)*Dm;
    ((float4*)(g_cat+base))[tid]=o;
    split4(o,(bf162*)(g_cat_h+base),(bf162*)(g_cat_l+base),2*(size_t)tid);
}
__global__ void __launch_bounds__(256) k_ln_ff(const float* __restrict__ gw, const float* __restrict__ bw){
    __shared__ float sh[8];
    int row=blockIdx.x, tid=threadIdx.x;
    size_t base=(size_t)row*Dm;
    float4 o=ln_core(((const float4*)(g_res+base))[tid],gw,bw,tid,sh);
    split4(o,(bf162*)(g_ffin_h+base),(bf162*)(g_ffin_l+base),2*(size_t)tid);
}
__global__ void __launch_bounds__(256) k_ln_final(const float* __restrict__ gw, const float* __restrict__ bw,
                                                  float* __restrict__ dout){
    __shared__ float sh[8];
    int row=blockIdx.x, tid=threadIdx.x;
    float4 a=((const float4*)(g_res+(size_t)row*Dm))[tid];
    float4 f=((const float4*)(g_ff2+(size_t)row*Dm))[tid];
    float4 o=ln_core(make_float4(a.x+f.x,a.y+f.y,a.z+f.z,a.w+f.w),gw,bw,tid,sh);
    float* dst=(row<RRm*BBm)?dout+S1_OFF+(size_t)row*Dm:dout+S0_OFF+(size_t)(row-RRm*BBm)*Dm;
    ((float4*)dst)[tid]=o;
}
__global__ void k_summary(){
    int e=blockIdx.x*blockDim.x+threadIdx.x;
    float s=0.f;
#pragma unroll 8
    for(int t=0;t<UUm;t++) s+=g_cat[(size_t)(36+t)*BD+e];
    float v=s*(1.f/SEGm);
    size_t o=(size_t)164*BD+e;
    bf16 h=__float2bfloat16(v);
    g_cat_h[o]=h; g_cat_l[o]=__float2bfloat16(v-__bfloat162float(h));
}

// ---- SIMT NT gemm (scores) ----
__global__ void __launch_bounds__(256) gemm_nt(
    const float* __restrict__ A, int lda, long sAz,
    const float* __restrict__ W, int ldw, long sWz,
    float* __restrict__ C, int ldc, long sCz, int M, int N, int K, float alpha)
{
    __shared__ float As[16][132];
    __shared__ float Ws[16][68];
    A+=(long)blockIdx.z*sAz; W+=(long)blockIdx.z*sWz; C+=(long)blockIdx.z*sCz;
    const int bm0=blockIdx.y*128, bn0=blockIdx.x*64;
    const int tid=threadIdx.x, tx=tid&15, ty=tid>>4;
    const int ar=tid>>1, ak=(tid&1)*8, wr=tid>>2, wk=(tid&3)*4;
    const bool av=(bm0+ar)<M, wv=(bn0+wr)<N;
    const float* Ap=A+(size_t)(bm0+ar)*lda+ak;
    const float* Wp=W+(size_t)(bn0+wr)*ldw+wk;
    float acc[8][4];
#pragma unroll
    for(int i=0;i<8;i++)
#pragma unroll
        for(int j=0;j<4;j++) acc[i][j]=0.f;
    for(int k0=0;k0<K;k0+=16){
        float4 a0=make_float4(0,0,0,0),a1=a0,w0=a0;
        if(av){a0=*(const float4*)(Ap+k0); a1=*(const float4*)(Ap+k0+4);}
        if(wv) w0=*(const float4*)(Wp+k0);
        As[ak+0][ar]=a0.x;As[ak+1][ar]=a0.y;As[ak+2][ar]=a0.z;As[ak+3][ar]=a0.w;
        As[ak+4][ar]=a1.x;As[ak+5][ar]=a1.y;As[ak+6][ar]=a1.z;As[ak+7][ar]=a1.w;
        Ws[wk+0][wr]=w0.x;Ws[wk+1][wr]=w0.y;Ws[wk+2][wr]=w0.z;Ws[wk+3][wr]=w0.w;
        __syncthreads();
#pragma unroll
        for(int kk=0;kk<16;kk++){
            float4 f0=*(const float4*)&As[kk][ty*8], f1=*(const float4*)&As[kk][ty*8+4];
            float4 bf=*(const float4*)&Ws[kk][tx*4];
            float avv[8]={f0.x,f0.y,f0.z,f0.w,f1.x,f1.y,f1.z,f1.w};
            float bv[4]={bf.x,bf.y,bf.z,bf.w};
#pragma unroll
            for(int i=0;i<8;i++)
#pragma unroll
                for(int j=0;j<4;j++) acc[i][j]+=avv[i]*bv[j];
        }
        __syncthreads();
    }
#pragma unroll
    for(int i=0;i<8;i++){
        int r=bm0+ty*8+i; if(r>=M) continue;
#pragma unroll
        for(int j=0;j<4;j++){
            int c=bn0+tx*4+j; if(c>=N) continue;
            C[(size_t)r*ldc+c]=acc[i][j]*alpha;
        }
    }
}
// ---- SIMT NN gemm (P@V) ----
__global__ void __launch_bounds__(256) gemm_nn(
    const float* __restrict__ A, int lda, long sAz,
    const float* __restrict__ Bm, int ldb, long sBz,
    float* __restrict__ C, int ldc, long sCz, int M, int N, int K)
{
    __shared__ float As[16][132];
    __shared__ float Bs[16][68];
    A+=(long)blockIdx.z*sAz; Bm+=(long)blockIdx.z*sBz; C+=(long)blockIdx.z*sCz;
    const int bm0=blockIdx.y*128, bn0=blockIdx.x*64;
    const int tid=threadIdx.x, tx=tid&15, ty=tid>>4;
    const int ar=tid>>1, ak=(tid&1)*8, br=tid>>4, bc=(tid&15)*4;
    const bool av=(bm0+ar)<M, bnv=(bn0+bc)<N;
    const float* Ap=A+(size_t)(bm0+ar)*lda+ak;
    float acc[8][4];
#pragma unroll
    for(int i=0;i<8;i++)
#pragma unroll
        for(int j=0;j<4;j++) acc[i][j]=0.f;
    for(int k0=0;k0<K;k0+=16){
        float4 a0=make_float4(0,0,0,0),a1=a0,b0=a0;
        if(av){ if(k0+ak<K) a0=*(const float4*)(Ap+k0); if(k0+ak+4<K) a1=*(const float4*)(Ap+k0+4); }
        if((k0+br)<K && bnv) b0=*(const float4*)(Bm+(size_t)(k0+br)*ldb+bn0+bc);
        As[ak+0][ar]=a0.x;As[ak+1][ar]=a0.y;As[ak+2][ar]=a0.z;As[ak+3][ar]=a0.w;
        As[ak+4][ar]=a1.x;As[ak+5][ar]=a1.y;As[ak+6][ar]=a1.z;As[ak+7][ar]=a1.w;
        Bs[br][bc+0]=b0.x;Bs[br][bc+1]=b0.y;Bs[br][bc+2]=b0.z;Bs[br][bc+3]=b0.w;
        __syncthreads();
#pragma unroll
        for(int kk=0;kk<16;kk++){
            float4 f0=*(const float4*)&As[kk][ty*8], f1=*(const float4*)&As[kk][ty*8+4];
            float4 bf=*(const float4*)&Bs[kk][tx*4];
            float avv[8]={f0.x,f0.y,f0.z,f0.w,f1.x,f1.y,f1.z,f1.w};
            float bv[4]={bf.x,bf.y,bf.z,bf.w};
#pragma unroll
            for(int i=0;i<8;i++)
#pragma unroll
                for(int j=0;j<4;j++) acc[i][j]+=avv[i]*bv[j];
        }
        __syncthreads();
    }
#pragma unroll
    for(int i=0;i<8;i++){
        int r=bm0+ty*8+i; if(r>=M) continue;
#pragma unroll
        for(int j=0;j<4;j++){
            int c=bn0+tx*4+j; if(c>=N) continue;
            C[(size_t)r*ldc+c]=acc[i][j];
        }
    }
}

__global__ void __launch_bounds__(128) k_softmax(const int* __restrict__ past_len){
    __shared__ float sred[4];
    int idx=blockIdx.x, q=idx%QQm, bh=idx/QQm;
    float* row=g_scores+(size_t)bh*(QQm*KKm)+(size_t)q*KKm;
    int pl=past_len[0], m_kv=min(LLm,pl), m_m=min(MMm,pl/SEGm);
    int tid=threadIdx.x, lane=tid&31, w=tid>>5;
    float v[4], mx=-3.4e38f;
#pragma unroll
    for(int j=0;j<4;j++){
        int c=tid+128*j; float val=-3.4e38f;
        if(c<KKm){
            bool msk=(c<MMm-m_m)||(c>=MMm+RRm && c<MMm+RRm+(LLm-m_kv))||(q==QQm-1 && c<MMm);
            val=msk?NEG_INF_F:row[c];
        }
        v[j]=val; mx=fmaxf(mx,val);
    }
#pragma unroll
    for(int o=16;o;o>>=1) mx=fmaxf(mx,__shfl_xor_sync(0xffffffffu,mx,o));
    if(lane==0) sred[w]=mx;
    __syncthreads();
    mx=fmaxf(fmaxf(sred[0],sred[1]),fmaxf(sred[2],sred[3]));
    __syncthreads();
    float s=0.f;
#pragma unroll
    for(int j=0;j<4;j++){ int c=tid+128*j; if(c<KKm){ v[j]=expf(v[j]-mx); s+=v[j]; } }
#pragma unroll
    for(int o=16;o;o>>=1) s+=__shfl_xor_sync(0xffffffffu,s,o);
    if(lane==0) sred[w]=s;
    __syncthreads();
    s=sred[0]+sred[1]+sred[2]+sred[3];
    float r=1.f/s;
#pragma unroll
    for(int j=0;j<4;j++){ int c=tid+128*j; if(c<KKm) row[c]=v[j]*r; }
}

extern "C" void kernel_launch(void* const* d_in, const int* in_sizes, int n_in,
                              void* d_out_v, int out_size) {
    const float* utterance=(const float*)d_in[0];
    const float* right_ctx=(const float*)d_in[1];
    const float* mems_in=(const float*)d_in[2];
    const float* state_mems=(const float*)d_in[3];
    const float* lc_key=(const float*)d_in[4];
    const float* lc_val=(const float*)d_in[5];
    const float* W_kv=(const float*)d_in[6];
    const float* b_kv=(const float*)d_in[7];
    const float* W_q=(const float*)d_in[8];
    const float* b_q=(const float*)d_in[9];
    const float* W_out=(const float*)d_in[10];
    const float* b_out=(const float*)d_in[11];
    const float* ln_in_g=(const float*)d_in[12];
    const float* ln_in_b=(const float*)d_in[13];
    const float* ln_ff_g=(const float*)d_in[14];
    const float* ln_ff_b=(const float*)d_in[15];
    const float* W_ff1=(const float*)d_in[16];
    const float* b_ff1=(const float*)d_in[17];
    const float* W_ff2=(const float*)d_in[18];
    const float* b_ff2=(const float*)d_in[19];
    const float* ln_out_g=(const float*)d_in[20];
    const float* ln_out_b=(const float*)d_in[21];
    const int* past_len=(const int*)d_in[22];
    float* dout=(float*)d_out_v;

    float *q,*k,*v,*scores,*attn,*res,*ff2b;
    bf16 *cath,*catl,*ffinh,*ffinl,*ffhh,*ffhl,*attnh,*attnl;
    bf16 *wqh,*wql,*wkvh,*wkvl,*woh,*wol,*w1h,*w1l,*w2h,*w2l;
    cudaGetSymbolAddress((void**)&q,g_q); cudaGetSymbolAddress((void**)&k,g_k);
    cudaGetSymbolAddress((void**)&v,g_v); cudaGetSymbolAddress((void**)&scores,g_scores);
    cudaGetSymbolAddress((void**)&attn,g_attn); cudaGetSymbolAddress((void**)&res,g_res);
    cudaGetSymbolAddress((void**)&ff2b,g_ff2);
    cudaGetSymbolAddress((void**)&cath,g_cat_h); cudaGetSymbolAddress((void**)&catl,g_cat_l);
    cudaGetSymbolAddress((void**)&ffinh,g_ffin_h); cudaGetSymbolAddress((void**)&ffinl,g_ffin_l);
    cudaGetSymbolAddress((void**)&ffhh,g_ffh_h); cudaGetSymbolAddress((void**)&ffhl,g_ffh_l);
    cudaGetSymbolAddress((void**)&attnh,g_attn_h); cudaGetSymbolAddress((void**)&attnl,g_attn_l);
    cudaGetSymbolAddress((void**)&wqh,g_wq_h); cudaGetSymbolAddress((void**)&wql,g_wq_l);
    cudaGetSymbolAddress((void**)&wkvh,g_wkv_h); cudaGetSymbolAddress((void**)&wkvl,g_wkv_l);
    cudaGetSymbolAddress((void**)&woh,g_wo_h); cudaGetSymbolAddress((void**)&wol,g_wo_l);
    cudaGetSymbolAddress((void**)&w1h,g_w1_h); cudaGetSymbolAddress((void**)&w1l,g_w1_l);
    cudaGetSymbolAddress((void**)&w2h,g_w2_h); cudaGetSymbolAddress((void**)&w2l,g_w2_l);

    cudaFuncSetAttribute(gemm_mma, cudaFuncAttributeMaxDynamicSharedMemorySize, GEMM_SMEM);

    // launches 1-5 (ncu -s 5 profiles launch #6 = gemm_mma Q)
    k_split<<<(4*BD/4)/256,256>>>(state_mems, cath, catl);            // 1
    k_split<<<(Dm*Dm/4)/256,256>>>(W_q, wqh, wql);                    // 2
    k_ln_in<<<TTm*BBm,256>>>(right_ctx, utterance, ln_in_g, ln_in_b); // 3
    k_summary<<<BD/256,256>>>();                                      // 4
    k_split<<<(2*Dm*Dm/4)/256,256>>>(W_kv, wkvh, wkvl);               // 5
    // 6: Q projection (PROFILED)
    gemm_mma<<<dim3(8,81),256,GEMM_SMEM>>>(cath+(size_t)4*BD, catl+(size_t)4*BD, Dm, wqh, wql, Dm,
        b_q, QQm*BBm, Dm, 0, q, nullptr, nullptr, Dm, nullptr, nullptr, nullptr, nullptr);
    // 7: merged KV projection (remap + mirror into dout)
    gemm_mma<<<dim3(16,82),256,GEMM_SMEM>>>(cath, catl, Dm, wkvh, wkvl, Dm,
        b_kv, 164*BBm, Dm, 2, nullptr, nullptr, nullptr, 0,
        k, v, dout+S4_OFF+(size_t)128*BD, dout+S5_OFF+(size_t)128*BD);
    cudaMemcpyAsync(k+(size_t)36*BD, lc_key, (size_t)LLm*BD*sizeof(float), cudaMemcpyDeviceToDevice, 0);
    cudaMemcpyAsync(v+(size_t)36*BD, lc_val, (size_t)LLm*BD*sizeof(float), cudaMemcpyDeviceToDevice, 0);
    k_split<<<(Dm*Dm/4)/256,256>>>(W_out, woh, wol);
    // attention (SIMT fp32)
    gemm_nt<<<dim3(7,2,1024),256>>>(q, BD, 64, k, BD, 64, scores, KKm, (long)QQm*KKm, QQm, KKm, 64, 0.125f);
    k_softmax<<<1024*QQm,128>>>(past_len);
    gemm_nn<<<dim3(1,2,1024),256>>>(scores, KKm, (long)QQm*KKm, v, BD, 64, attn, BD, 64, QQm, 64, KKm);
    // out projection with fused residual + clip (mode 3)
    k_split<<<((size_t)QQm*BD/4)/256,256>>>(attn, attnh, attnl);
    gemm_mma<<<dim3(8,81),256,GEMM_SMEM>>>(attnh, attnl, Dm, woh, wol, Dm,
        b_out, QQm*BBm, Dm, 3, res, nullptr, nullptr, Dm,
        (float*)right_ctx, (float*)utterance, dout+S2_OFF, nullptr);
    // FFN
    k_ln_ff<<<TTm*BBm,256>>>(ln_ff_g, ln_ff_b);
    k_split<<<((size_t)FFNm*Dm/4)/256,256>>>(W_ff1, w1h, w1l);
    gemm_mma<<<dim3(32,80),256,GEMM_SMEM>>>(ffinh, ffinl, Dm, w1h, w1l, Dm,
        b_ff1, TTm*BBm, Dm, 1, nullptr, ffhh, ffhl, FFNm, nullptr, nullptr, nullptr, nullptr);
    k_split<<<((size_t)FFNm*Dm/4)/256,256>>>(W_ff2, w2h, w2l);
    gemm_mma<<<dim3(8,80),256,GEMM_SMEM>>>(ffhh, ffhl, FFNm, w2h, w2l, FFNm,
        b_ff2, TTm*BBm, FFNm, 0, ff2b, nullptr, nullptr, Dm, nullptr, nullptr, nullptr, nullptr);
    k_ln_final<<<TTm*BBm,256>>>(ln_out_g, ln_out_b, dout);
    // state-carry
    cudaMemcpyAsync(dout+S3_OFF, state_mems+BD, (size_t)3*BD*sizeof(float), cudaMemcpyDeviceToDevice, 0);
    cudaMemcpyAsync(dout+S3_OFF+(size_t)3*BD, mems_in, (size_t)BD*sizeof(float), cudaMemcpyDeviceToDevice, 0);
    cudaMemcpyAsync(dout+S4_OFF, lc_key+(size_t)128*BD, (size_t)128*BD*sizeof(float), cudaMemcpyDeviceToDevice, 0);
    cudaMemcpyAsync(dout+S5_OFF, lc_val+(size_t)128*BD, (size_t)128*BD*sizeof(float), cudaMemcpyDeviceToDevice, 0);
}